// round 8
// baseline (speedup 1.0000x reference)
#include <cuda_runtime.h>
#include <cuda_fp16.h>
#include <cuda_fp8.h>
#include <math.h>

#define BB 8
#define NN 2048
#define DD 128
#define SPLIT 8
#define TWO_PI_F 6.283185307179586f

// Static device scratch (no allocations allowed).
__device__ unsigned char d_C8[(size_t)BB * NN * NN];  // coupling e4m3, normal layout (full, via mirror)
__device__ unsigned char d_Cf[(size_t)BB * NN * NN];  // coupling e4m3 in m16n8k32 A-fragment layout
__device__ float d_theta_buf[2 * BB * NN];            // ping-pong theta
__device__ unsigned char d_cosF8[BB * NN];            // cos(theta) e4m3 (MMA B operand)
__device__ unsigned char d_sinF8[BB * NN];            // sin(theta) e4m3
__device__ float d_partC[BB * 16 * SPLIT * 128];      // per-(b,rowgroup,split) partials
__device__ float d_partS[BB * 16 * SPLIT * 128];
__device__ int   d_cnt[BB * 16];                      // arrival counters (BSS=0)

// ---- packed f32x2 helpers (Blackwell FFMA2, used in build) ----
static __device__ __forceinline__ unsigned long long pack2(float lo, float hi) {
    unsigned long long r;
    asm("mov.b64 %0, {%1, %2};" : "=l"(r) : "f"(lo), "f"(hi));
    return r;
}
static __device__ __forceinline__ void unpack2(unsigned long long v, float& lo, float& hi) {
    asm("mov.b64 {%0, %1}, %2;" : "=f"(lo), "=f"(hi) : "l"(v));
}
static __device__ __forceinline__ void fma2(unsigned long long& d,
                                            unsigned long long a,
                                            unsigned long long b) {
    asm("fma.rn.f32x2 %0, %1, %2, %0;" : "+l"(d) : "l"(a), "l"(b));
}

// coupling ≈ x - sqrt(x^2-1), x = max(-lz, 1+1e-7)
__device__ __forceinline__ float coupling_from_lz(float lz) {
    float x = fmaxf(-lz, 1.0f + 1e-7f);
    float t = (x - 1.0f) * (x + 1.0f);
    float xh = 0.5f * t;
    float r = __int_as_float(0x5f375a86 - (__float_as_int(t) >> 1));
    r = r * (1.5f - xh * r * r);
    r = r * (1.5f - xh * r * r);
    r = r * (1.5f - xh * r * r);
    float s = t * r;
    float c = x - s;
    return fminf(fmaxf(c, 0.0f), 1.0f);
}

static __device__ __forceinline__ unsigned fp8x4_from_floats(float c0, float c1,
                                                             float c2, float c3) {
    __nv_fp8x2_storage_t p01 =
        __nv_cvt_float2_to_fp8x2(make_float2(c0, c1), __NV_SATFINITE, __NV_E4M3);
    __nv_fp8x2_storage_t p23 =
        __nv_cvt_float2_to_fp8x2(make_float2(c2, c3), __NV_SATFINITE, __NV_E4M3);
    return (unsigned)p01 | ((unsigned)p23 << 16);
}

#define BM 64
#define BN 64
#define BK 32

// Build C for upper-triangle 128-tiles; strictly-upper blocks also write the
// transposed mirror (normal layout ends up FULL symmetric).
__global__ void build_coupling_kernel(const float* __restrict__ emb) {
    int m128 = blockIdx.x >> 1;
    int n128 = blockIdx.y >> 1;
    if (m128 < n128) return;
    bool twrite = (m128 > n128);

    int b  = blockIdx.z;
    int n0 = blockIdx.y * BM;
    int m0 = blockIdx.x * BN;
    const float* E = emb + (size_t)b * NN * DD;

    __shared__ __align__(16) float As[BK][BM];
    __shared__ __align__(16) float Bs[BK][BN];
    __shared__ unsigned shT[64 * 17];

    int tx = threadIdx.x, ty = threadIdx.y;    // block (16,16)
    int tid = ty * 16 + tx;
    int loadRow = tid >> 3;
    int loadK   = (tid & 7) * 4;

    unsigned long long acc[4][2] = {};

    for (int k0 = 0; k0 < DD; k0 += BK) {
        #pragma unroll
        for (int rr = 0; rr < 2; rr++) {
            int row = loadRow + rr * 32;
            float4 v = *(const float4*)(E + (size_t)(n0 + row) * DD + k0 + loadK);
            if (k0 == 0 && loadK == 0) v.x = -v.x;
            As[loadK + 0][row] = v.x;
            As[loadK + 1][row] = v.y;
            As[loadK + 2][row] = v.z;
            As[loadK + 3][row] = v.w;
            float4 w = *(const float4*)(E + (size_t)(m0 + row) * DD + k0 + loadK);
            Bs[loadK + 0][row] = w.x;
            Bs[loadK + 1][row] = w.y;
            Bs[loadK + 2][row] = w.z;
            Bs[loadK + 3][row] = w.w;
        }
        __syncthreads();

        #pragma unroll
        for (int kk = 0; kk < BK; kk++) {
            float4 a4 = *(const float4*)&As[kk][ty * 4];
            ulonglong2 b2 = *(const ulonglong2*)&Bs[kk][tx * 4];
            unsigned long long a0 = pack2(a4.x, a4.x);
            unsigned long long a1 = pack2(a4.y, a4.y);
            unsigned long long a2 = pack2(a4.z, a4.z);
            unsigned long long a3 = pack2(a4.w, a4.w);
            fma2(acc[0][0], a0, b2.x); fma2(acc[0][1], a0, b2.y);
            fma2(acc[1][0], a1, b2.x); fma2(acc[1][1], a1, b2.y);
            fma2(acc[2][0], a2, b2.x); fma2(acc[2][1], a2, b2.y);
            fma2(acc[3][0], a3, b2.x); fma2(acc[3][1], a3, b2.y);
        }
        __syncthreads();
    }

    #pragma unroll
    for (int i = 0; i < 4; i++) {
        int n = n0 + ty * 4 + i;
        float c0, c1, c2, c3;
        unpack2(acc[i][0], c0, c1);
        unpack2(acc[i][1], c2, c3);
        c0 = coupling_from_lz(c0);
        c1 = coupling_from_lz(c1);
        c2 = coupling_from_lz(c2);
        c3 = coupling_from_lz(c3);
        unsigned o = fp8x4_from_floats(c0, c1, c2, c3);
        *(unsigned*)(d_C8 + ((size_t)b * NN + n) * NN + m0 + tx * 4) = o;
        if (twrite) shT[(ty * 4 + i) * 17 + tx] = o;
    }

    if (twrite) {
        __syncthreads();
        #pragma unroll
        for (int k = 0; k < 4; k++) {
            int idx = k * 256 + tid;
            int mm = idx >> 4;
            int qn = idx & 15;
            int word = mm >> 2, sh = (mm & 3) * 8;
            unsigned u0 = shT[(qn * 4 + 0) * 17 + word];
            unsigned u1 = shT[(qn * 4 + 1) * 17 + word];
            unsigned u2 = shT[(qn * 4 + 2) * 17 + word];
            unsigned u3 = shT[(qn * 4 + 3) * 17 + word];
            unsigned o = ((u0 >> sh) & 0xFFu)
                       | (((u1 >> sh) & 0xFFu) << 8)
                       | (((u2 >> sh) & 0xFFu) << 16)
                       | (((u3 >> sh) & 0xFFu) << 24);
            *(unsigned*)(d_C8 + ((size_t)b * NN + m0 + mm) * NN + n0 + qn * 4) = o;
        }
    }
}

// Repack normal-layout fp8 C into m16n8k32 A-fragment layout.
// Tile (mt,kt) is 16 rows x 32 k-bytes = 512 B; lane l (gid=l>>2, tig=l&3):
//   a0 = A[gid][tig*4..+3], a1 = A[gid+8][tig*4..+3],
//   a2 = A[gid][16+tig*4..+3], a3 = A[gid+8][16+tig*4..+3]
#define RP_PITCH 144
__global__ void __launch_bounds__(256) repack_kernel() {
    __shared__ unsigned char sh[128 * RP_PITCH];
    int b = blockIdx.z, MT = blockIdx.y, KT = blockIdx.x;    // 16 x 16
    int tid = threadIdx.x;
    const unsigned char* src = d_C8 + ((size_t)b * NN + MT * 128) * NN + KT * 128;

    #pragma unroll
    for (int i = 0; i < 4; i++) {
        int idx = tid + i * 256;          // 1024 uint4 = 128 rows x 8
        int r = idx >> 3, q = idx & 7;
        uint4 v = *(const uint4*)(src + (size_t)r * NN + q * 16);
        *(uint4*)(sh + r * RP_PITCH + q * 16) = v;
    }
    __syncthreads();

    int lane = tid & 31, w = tid >> 5;
    int gid = lane >> 2, tig = lane & 3;
    #pragma unroll
    for (int s = 0; s < 4; s++) {
        int tt  = s * 8 + w;              // 0..31 local tiles
        int mtl = tt >> 2, ktl = tt & 3;  // 8 m-tiles x 4 k-slabs
        const unsigned char* base = sh + (mtl * 16 + gid) * RP_PITCH + ktl * 32 + tig * 4;
        uint4 o;
        o.x = *(const unsigned*)(base);
        o.y = *(const unsigned*)(base + 8 * RP_PITCH);
        o.z = *(const unsigned*)(base + 16);
        o.w = *(const unsigned*)(base + 8 * RP_PITCH + 16);
        size_t toff = (((size_t)(b * 128 + MT * 8 + mtl)) * 64 + KT * 4 + ktl) * 512
                    + (size_t)lane * 16;
        *(uint4*)(d_Cf + toff) = o;
    }
}

__global__ void init_trig_kernel(const float* __restrict__ th) {
    int i = blockIdx.x * 256 + threadIdx.x;
    float s, c;
    sincosf(th[i], &s, &c);
    d_cosF8[i] = (unsigned char)__nv_cvt_float_to_fp8(c, __NV_SATFINITE, __NV_E4M3);
    d_sinF8[i] = (unsigned char)__nv_cvt_float_to_fp8(s, __NV_SATFINITE, __NV_E4M3);
}

// Step via native e4m3 MMA with DEEP PREFETCH: all 8 k-slab fragments for a
// warp's m-tile are loaded into registers (8 x uint4 = 32 regs in flight)
// before the MMA chain. Grid (rowgroup=16, split=8, batch=8) = 1024 blocks.
__global__ void __launch_bounds__(256, 3)
step_kernel(const float* __restrict__ th_in,
            float* __restrict__ th_out,
            const float* __restrict__ omega) {
    __shared__ unsigned shTrig[136];       // cos words [0..63], sin words [68..131]
    __shared__ int isLast;

    int rg = blockIdx.x, sp = blockIdx.y, b = blockIdx.z;
    int tid = threadIdx.x;
    int w = tid >> 5, lane = tid & 31;
    int gid = lane >> 2, tig = lane & 3;

    // stage this split's 256 trig fp8 bytes (64 words each)
    if (tid < 64)
        shTrig[tid] = ((const unsigned*)(d_cosF8 + (size_t)b * NN + sp * 256))[tid];
    else if (tid < 128)
        shTrig[68 + tid - 64] = ((const unsigned*)(d_sinF8 + (size_t)b * NN + sp * 256))[tid - 64];
    __syncthreads();

    const unsigned* bp = (gid == 1) ? (shTrig + 68) : shTrig;

    int mt = rg * 8 + w;                   // global m-tile 0..127
    const uint4* Af = (const uint4*)(d_Cf
        + (((size_t)(b * 128 + mt)) * 64 + sp * 8) * 512) + lane;

    // deep prefetch: all 8 fragment loads issued before any MMA
    uint4 a[8];
    #pragma unroll
    for (int it = 0; it < 8; it++) a[it] = Af[it * 32];

    unsigned bw0[8], bw1[8];
    #pragma unroll
    for (int it = 0; it < 8; it++) {
        bw0[it] = bp[it * 8 + tig];
        bw1[it] = bp[it * 8 + tig + 4];
    }

    float d0 = 0.f, d1 = 0.f, d2 = 0.f, d3 = 0.f;
    #pragma unroll
    for (int it = 0; it < 8; it++) {       // 8 k32-slabs = 256 rows
        asm volatile(
            "mma.sync.aligned.m16n8k32.row.col.f32.e4m3.e4m3.f32 "
            "{%0,%1,%2,%3}, {%4,%5,%6,%7}, {%8,%9}, {%0,%1,%2,%3};"
            : "+f"(d0), "+f"(d1), "+f"(d2), "+f"(d3)
            : "r"(a[it].x), "r"(a[it].y), "r"(a[it].z), "r"(a[it].w),
              "r"(bw0[it]), "r"(bw1[it]));
    }

    // lanes with tig==0 hold cols 0,1 = (yc, ys) for rows gid and gid+8
    if (tig == 0) {
        int lr = w * 16 + gid;
        size_t pb = (((size_t)(b * 16 + rg)) * SPLIT + sp) * 128;
        d_partC[pb + lr]     = d0;
        d_partS[pb + lr]     = d1;
        d_partC[pb + lr + 8] = d2;
        d_partS[pb + lr + 8] = d3;
    }
    __threadfence();
    __syncthreads();

    if (tid == 0) {
        int old = atomicAdd(&d_cnt[b * 16 + rg], 1);
        isLast = (old == SPLIT - 1);
    }
    __syncthreads();

    if (isLast) {
        __threadfence();
        if (tid < 128) {
            size_t base = ((size_t)(b * 16 + rg)) * SPLIT * 128 + tid;
            float yc = 0.f, ys = 0.f;
            #pragma unroll
            for (int s = 0; s < SPLIT; s++) {   // fixed order -> deterministic
                yc += d_partC[base + (size_t)s * 128];
                ys += d_partS[base + (size_t)s * 128];
            }
            int n  = rg * 128 + tid;
            int gi = b * NN + n;
            float th = th_in[gi];
            float sn, cn;
            sincosf(th, &sn, &cn);
            float csum = sn * yc - cn * ys;
            float dth = omega[n] + (1.0f / NN) * csum;
            float thn = fmodf(th + 0.1f * dth, TWO_PI_F);
            th_out[gi] = thn;
            float s2, c2;
            sincosf(thn, &s2, &c2);
            d_cosF8[gi] = (unsigned char)__nv_cvt_float_to_fp8(c2, __NV_SATFINITE, __NV_E4M3);
            d_sinF8[gi] = (unsigned char)__nv_cvt_float_to_fp8(s2, __NV_SATFINITE, __NV_E4M3);
        }
        if (tid == 0) d_cnt[b * 16 + rg] = 0;   // ready for next step / replay
    }
}

extern "C" void kernel_launch(void* const* d_in, const int* in_sizes, int n_in,
                              void* d_out, int out_size) {
    const float* initial = (const float*)d_in[0];   // (B,N)
    const float* emb     = (const float*)d_in[1];   // (B,N,D)
    const float* omega   = (const float*)d_in[2];   // (N,)
    float* out = (float*)d_out;                     // (B,N)

    float* buf = nullptr;
    cudaGetSymbolAddress((void**)&buf, d_theta_buf);

    dim3 bgrid(NN / BN, NN / BM, BB);
    dim3 bblock(16, 16);
    build_coupling_kernel<<<bgrid, bblock>>>(emb);

    dim3 rgrid(16, 16, BB);
    repack_kernel<<<rgrid, 256>>>();

    init_trig_kernel<<<BB * NN / 256, 256>>>(initial);

    dim3 sgrid(16, SPLIT, BB);
    for (int k = 0; k < 16; k++) {
        const float* src = (k == 0)  ? initial : buf + ((k + 1) & 1) * BB * NN;
        float*       dst = (k == 15) ? out     : buf + (k & 1) * BB * NN;
        step_kernel<<<sgrid, 256>>>(src, dst, omega);
    }
}

// round 9
// speedup vs baseline: 1.1642x; 1.1642x over previous
#include <cuda_runtime.h>
#include <cuda_fp16.h>
#include <cuda_fp8.h>
#include <math.h>

#define BB 8
#define NN 2048
#define DD 128
#define TWO_PI_F 6.283185307179586f

// Static device scratch (no allocations allowed).
__device__ unsigned char d_C8[(size_t)BB * NN * NN];  // coupling e4m3, normal layout (full, via mirror)
__device__ unsigned char d_Cf[(size_t)BB * NN * NN];  // coupling e4m3 in m16n8k32 A-fragment layout
__device__ float d_theta_buf[2 * BB * NN];            // ping-pong theta
__device__ unsigned char d_cosF8[BB * NN];            // cos(theta) e4m3 (MMA B operand)
__device__ unsigned char d_sinF8[BB * NN];            // sin(theta) e4m3

// ---- packed f32x2 helpers (Blackwell FFMA2, used in build) ----
static __device__ __forceinline__ unsigned long long pack2(float lo, float hi) {
    unsigned long long r;
    asm("mov.b64 %0, {%1, %2};" : "=l"(r) : "f"(lo), "f"(hi));
    return r;
}
static __device__ __forceinline__ void unpack2(unsigned long long v, float& lo, float& hi) {
    asm("mov.b64 {%0, %1}, %2;" : "=f"(lo), "=f"(hi) : "l"(v));
}
static __device__ __forceinline__ void fma2(unsigned long long& d,
                                            unsigned long long a,
                                            unsigned long long b) {
    asm("fma.rn.f32x2 %0, %1, %2, %0;" : "+l"(d) : "l"(a), "l"(b));
}

// coupling ≈ x - sqrt(x^2-1), x = max(-lz, 1+1e-7)
__device__ __forceinline__ float coupling_from_lz(float lz) {
    float x = fmaxf(-lz, 1.0f + 1e-7f);
    float t = (x - 1.0f) * (x + 1.0f);
    float xh = 0.5f * t;
    float r = __int_as_float(0x5f375a86 - (__float_as_int(t) >> 1));
    r = r * (1.5f - xh * r * r);
    r = r * (1.5f - xh * r * r);
    r = r * (1.5f - xh * r * r);
    float s = t * r;
    float c = x - s;
    return fminf(fmaxf(c, 0.0f), 1.0f);
}

static __device__ __forceinline__ unsigned fp8x4_from_floats(float c0, float c1,
                                                             float c2, float c3) {
    __nv_fp8x2_storage_t p01 =
        __nv_cvt_float2_to_fp8x2(make_float2(c0, c1), __NV_SATFINITE, __NV_E4M3);
    __nv_fp8x2_storage_t p23 =
        __nv_cvt_float2_to_fp8x2(make_float2(c2, c3), __NV_SATFINITE, __NV_E4M3);
    return (unsigned)p01 | ((unsigned)p23 << 16);
}

#define BM 64
#define BN 64
#define BK 32

// Build C for upper-triangle 128-tiles; strictly-upper blocks also write the
// transposed mirror (normal layout ends up FULL symmetric).
__global__ void build_coupling_kernel(const float* __restrict__ emb) {
    int m128 = blockIdx.x >> 1;
    int n128 = blockIdx.y >> 1;
    if (m128 < n128) return;
    bool twrite = (m128 > n128);

    int b  = blockIdx.z;
    int n0 = blockIdx.y * BM;
    int m0 = blockIdx.x * BN;
    const float* E = emb + (size_t)b * NN * DD;

    __shared__ __align__(16) float As[BK][BM];
    __shared__ __align__(16) float Bs[BK][BN];
    __shared__ unsigned shT[64 * 17];

    int tx = threadIdx.x, ty = threadIdx.y;    // block (16,16)
    int tid = ty * 16 + tx;
    int loadRow = tid >> 3;
    int loadK   = (tid & 7) * 4;

    unsigned long long acc[4][2] = {};

    for (int k0 = 0; k0 < DD; k0 += BK) {
        #pragma unroll
        for (int rr = 0; rr < 2; rr++) {
            int row = loadRow + rr * 32;
            float4 v = *(const float4*)(E + (size_t)(n0 + row) * DD + k0 + loadK);
            if (k0 == 0 && loadK == 0) v.x = -v.x;
            As[loadK + 0][row] = v.x;
            As[loadK + 1][row] = v.y;
            As[loadK + 2][row] = v.z;
            As[loadK + 3][row] = v.w;
            float4 w = *(const float4*)(E + (size_t)(m0 + row) * DD + k0 + loadK);
            Bs[loadK + 0][row] = w.x;
            Bs[loadK + 1][row] = w.y;
            Bs[loadK + 2][row] = w.z;
            Bs[loadK + 3][row] = w.w;
        }
        __syncthreads();

        #pragma unroll
        for (int kk = 0; kk < BK; kk++) {
            float4 a4 = *(const float4*)&As[kk][ty * 4];
            ulonglong2 b2 = *(const ulonglong2*)&Bs[kk][tx * 4];
            unsigned long long a0 = pack2(a4.x, a4.x);
            unsigned long long a1 = pack2(a4.y, a4.y);
            unsigned long long a2 = pack2(a4.z, a4.z);
            unsigned long long a3 = pack2(a4.w, a4.w);
            fma2(acc[0][0], a0, b2.x); fma2(acc[0][1], a0, b2.y);
            fma2(acc[1][0], a1, b2.x); fma2(acc[1][1], a1, b2.y);
            fma2(acc[2][0], a2, b2.x); fma2(acc[2][1], a2, b2.y);
            fma2(acc[3][0], a3, b2.x); fma2(acc[3][1], a3, b2.y);
        }
        __syncthreads();
    }

    #pragma unroll
    for (int i = 0; i < 4; i++) {
        int n = n0 + ty * 4 + i;
        float c0, c1, c2, c3;
        unpack2(acc[i][0], c0, c1);
        unpack2(acc[i][1], c2, c3);
        c0 = coupling_from_lz(c0);
        c1 = coupling_from_lz(c1);
        c2 = coupling_from_lz(c2);
        c3 = coupling_from_lz(c3);
        unsigned o = fp8x4_from_floats(c0, c1, c2, c3);
        *(unsigned*)(d_C8 + ((size_t)b * NN + n) * NN + m0 + tx * 4) = o;
        if (twrite) shT[(ty * 4 + i) * 17 + tx] = o;
    }

    if (twrite) {
        __syncthreads();
        #pragma unroll
        for (int k = 0; k < 4; k++) {
            int idx = k * 256 + tid;
            int mm = idx >> 4;
            int qn = idx & 15;
            int word = mm >> 2, sh = (mm & 3) * 8;
            unsigned u0 = shT[(qn * 4 + 0) * 17 + word];
            unsigned u1 = shT[(qn * 4 + 1) * 17 + word];
            unsigned u2 = shT[(qn * 4 + 2) * 17 + word];
            unsigned u3 = shT[(qn * 4 + 3) * 17 + word];
            unsigned o = ((u0 >> sh) & 0xFFu)
                       | (((u1 >> sh) & 0xFFu) << 8)
                       | (((u2 >> sh) & 0xFFu) << 16)
                       | (((u3 >> sh) & 0xFFu) << 24);
            *(unsigned*)(d_C8 + ((size_t)b * NN + m0 + mm) * NN + n0 + qn * 4) = o;
        }
    }
}

// Repack normal-layout fp8 C into m16n8k32 A-fragment layout.
// Tile (mt,kt) is 16 rows x 32 k-bytes = 512 B; lane l (gid=l>>2, tig=l&3):
//   a0 = A[gid][tig*4..+3], a1 = A[gid+8][tig*4..+3],
//   a2 = A[gid][16+tig*4..+3], a3 = A[gid+8][16+tig*4..+3]
#define RP_PITCH 144
__global__ void __launch_bounds__(256) repack_kernel() {
    __shared__ unsigned char sh[128 * RP_PITCH];
    int b = blockIdx.z, MT = blockIdx.y, KT = blockIdx.x;    // 16 x 16
    int tid = threadIdx.x;
    const unsigned char* src = d_C8 + ((size_t)b * NN + MT * 128) * NN + KT * 128;

    #pragma unroll
    for (int i = 0; i < 4; i++) {
        int idx = tid + i * 256;          // 1024 uint4 = 128 rows x 8
        int r = idx >> 3, q = idx & 7;
        uint4 v = *(const uint4*)(src + (size_t)r * NN + q * 16);
        *(uint4*)(sh + r * RP_PITCH + q * 16) = v;
    }
    __syncthreads();

    int lane = tid & 31, w = tid >> 5;
    int gid = lane >> 2, tig = lane & 3;
    #pragma unroll
    for (int s = 0; s < 4; s++) {
        int tt  = s * 8 + w;              // 0..31 local tiles
        int mtl = tt >> 2, ktl = tt & 3;  // 8 m-tiles x 4 k-slabs
        const unsigned char* base = sh + (mtl * 16 + gid) * RP_PITCH + ktl * 32 + tig * 4;
        uint4 o;
        o.x = *(const unsigned*)(base);
        o.y = *(const unsigned*)(base + 8 * RP_PITCH);
        o.z = *(const unsigned*)(base + 16);
        o.w = *(const unsigned*)(base + 8 * RP_PITCH + 16);
        size_t toff = (((size_t)(b * 128 + MT * 8 + mtl)) * 64 + KT * 4 + ktl) * 512
                    + (size_t)lane * 16;
        *(uint4*)(d_Cf + toff) = o;
    }
}

__global__ void init_trig_kernel(const float* __restrict__ th) {
    int i = blockIdx.x * 256 + threadIdx.x;
    float s, c;
    sincosf(th[i], &s, &c);
    d_cosF8[i] = (unsigned char)__nv_cvt_float_to_fp8(c, __NV_SATFINITE, __NV_E4M3);
    d_sinF8[i] = (unsigned char)__nv_cvt_float_to_fp8(s, __NV_SATFINITE, __NV_E4M3);
}

// Step, self-contained per block: grid (16 rg, 8 b) = 128 blocks, 512 threads
// = 16 warps = 8 m-tiles x 2 k-half warps. Rolling depth-8 register pipeline
// streams a CONTIGUOUS 256KB slice of d_Cf per block. Intra-block shared
// reduction only: no atomics, no threadfence, no global partials.
__global__ void __launch_bounds__(512, 1)
step_kernel(const float* __restrict__ th_in,
            float* __restrict__ th_out,
            const float* __restrict__ omega) {
    __shared__ unsigned shCos[512];            // 2048 fp8 cos bytes
    __shared__ unsigned shSin[512];
    __shared__ float shPC[2][128];
    __shared__ float shPS[2][128];

    int rg = blockIdx.x, b = blockIdx.y;
    int tid = threadIdx.x;
    int w = tid >> 5, lane = tid & 31;
    int gid = lane >> 2, tig = lane & 3;
    int mtl = w & 7, kq = w >> 3;              // m-tile 0..7, k-half 0..1

    shCos[tid] = ((const unsigned*)(d_cosF8 + (size_t)b * NN))[tid];
    shSin[tid] = ((const unsigned*)(d_sinF8 + (size_t)b * NN))[tid];
    __syncthreads();

    const unsigned* bp = (gid == 1) ? shSin : shCos;
    int bbase = kq * 256 + tig;                // word index of slab 0 for this warp

    int mt = rg * 8 + mtl;
    const uint4* Af = (const uint4*)(d_Cf
        + (((size_t)(b * 128 + mt)) * 64 + kq * 32) * 512) + lane;

    // rolling depth-8 pipeline over 32 k-slabs (512B each, stride 32 uint4)
    uint4 a[8];
    #pragma unroll
    for (int i = 0; i < 8; i++) a[i] = Af[i * 32];

    float d0 = 0.f, d1 = 0.f, d2 = 0.f, d3 = 0.f;
    #pragma unroll
    for (int it = 0; it < 32; it++) {
        uint4 cur = a[it & 7];
        if (it + 8 < 32) a[it & 7] = Af[(it + 8) * 32];
        unsigned b0 = bp[bbase + it * 8];
        unsigned b1 = bp[bbase + it * 8 + 4];
        asm volatile(
            "mma.sync.aligned.m16n8k32.row.col.f32.e4m3.e4m3.f32 "
            "{%0,%1,%2,%3}, {%4,%5,%6,%7}, {%8,%9}, {%0,%1,%2,%3};"
            : "+f"(d0), "+f"(d1), "+f"(d2), "+f"(d3)
            : "r"(cur.x), "r"(cur.y), "r"(cur.z), "r"(cur.w), "r"(b0), "r"(b1));
    }

    // lanes with tig==0 hold cols 0,1 = (yc, ys) for rows gid and gid+8
    if (tig == 0) {
        int lr = mtl * 16 + gid;
        shPC[kq][lr]     = d0;
        shPS[kq][lr]     = d1;
        shPC[kq][lr + 8] = d2;
        shPS[kq][lr + 8] = d3;
    }
    __syncthreads();

    if (tid < 128) {
        float yc = shPC[0][tid] + shPC[1][tid];   // fixed order -> deterministic
        float ys = shPS[0][tid] + shPS[1][tid];
        int n  = rg * 128 + tid;
        int gi = b * NN + n;
        float th = th_in[gi];
        float sn, cn;
        sincosf(th, &sn, &cn);
        float csum = sn * yc - cn * ys;
        float dth = omega[n] + (1.0f / NN) * csum;
        float thn = fmodf(th + 0.1f * dth, TWO_PI_F);
        th_out[gi] = thn;
        float s2, c2;
        sincosf(thn, &s2, &c2);
        d_cosF8[gi] = (unsigned char)__nv_cvt_float_to_fp8(c2, __NV_SATFINITE, __NV_E4M3);
        d_sinF8[gi] = (unsigned char)__nv_cvt_float_to_fp8(s2, __NV_SATFINITE, __NV_E4M3);
    }
}

extern "C" void kernel_launch(void* const* d_in, const int* in_sizes, int n_in,
                              void* d_out, int out_size) {
    const float* initial = (const float*)d_in[0];   // (B,N)
    const float* emb     = (const float*)d_in[1];   // (B,N,D)
    const float* omega   = (const float*)d_in[2];   // (N,)
    float* out = (float*)d_out;                     // (B,N)

    float* buf = nullptr;
    cudaGetSymbolAddress((void**)&buf, d_theta_buf);

    dim3 bgrid(NN / BN, NN / BM, BB);
    dim3 bblock(16, 16);
    build_coupling_kernel<<<bgrid, bblock>>>(emb);

    dim3 rgrid(16, 16, BB);
    repack_kernel<<<rgrid, 256>>>();

    init_trig_kernel<<<BB * NN / 256, 256>>>(initial);

    dim3 sgrid(16, BB);
    for (int k = 0; k < 16; k++) {
        const float* src = (k == 0)  ? initial : buf + ((k + 1) & 1) * BB * NN;
        float*       dst = (k == 15) ? out     : buf + (k & 1) * BB * NN;
        step_kernel<<<sgrid, 512>>>(src, dst, omega);
    }
}